// round 8
// baseline (speedup 1.0000x reference)
#include <cuda_runtime.h>

typedef unsigned long long ull;

#define HID 10
#define BATCH 16384
#define TPAIRS 1024
#define TPB 128

// ---------- g_pack / c_w layout (250 longlong2), identical to r7 ----------
#define OFF_WHB   0
#define OFF_WHA   80
#define OFF_WHB89 160
#define OFF_WHA89 180
#define OFF_WXB   200
#define OFF_WXA0  210
#define OFF_WXA1  220
#define OFF_BB    230
#define OFF_BA    240

__constant__ longlong2 c_w[250];
__device__   longlong2 g_pack[250];

// ---------- packed fp32x2 helpers ----------
__device__ __forceinline__ ull pack2(float lo, float hi){
    ull r; asm("mov.b64 %0, {%1, %2};" : "=l"(r) : "f"(lo), "f"(hi)); return r;
}
__device__ __forceinline__ ull bcast2(float v){
    ull r; asm("mov.b64 %0, {%1, %1};" : "=l"(r) : "f"(v)); return r;
}
__device__ __forceinline__ void unpack2(ull v, float &lo, float &hi){
    asm("mov.b64 {%0, %1}, %2;" : "=f"(lo), "=f"(hi) : "l"(v));
}
__device__ __forceinline__ ull ffma2(ull a, ull b, ull c){
    ull d; asm("fma.rn.f32x2 %0, %1, %2, %3;" : "=l"(d) : "l"(a), "l"(b), "l"(c)); return d;
}
__device__ __forceinline__ float tanh_ap(float x){
    float r; asm("tanh.approx.f32 %0, %1;" : "=f"(r) : "f"(x)); return r;
}

// ---------- pack kernel (identical to r7, known-good) ----------
__global__ void pack_kernel(
    const float* __restrict__ WihA, const float* __restrict__ WhhA,
    const float* __restrict__ bihA, const float* __restrict__ bhhA,
    const float* __restrict__ WihB, const float* __restrict__ WhhB,
    const float* __restrict__ bihB, const float* __restrict__ bhhB)
{
    int idx = threadIdx.x;
    if (idx < 160){
        int cell = idx / 80;
        int rem  = idx % 80;           // jj*10 + r*5 + p
        int jj = rem / 10;
        int r  = (rem % 10) / 5;
        int p  = rem % 5;
        int aj = (jj < 5) ? (5*r + jj) : (5*(1-r) + (jj-5));
        int d  = 5*r + p;
        const float* W = cell ? WhhA : WhhB;
        g_pack[(cell ? OFF_WHA : OFF_WHB) + rem] = make_longlong2(
            (long long)pack2(0.5f*W[(      d)*HID + aj], 0.5f*W[(  HID+d)*HID + aj]),
            (long long)pack2(     W[(2*HID+d)*HID + aj], 0.5f*W[(3*HID+d)*HID + aj]));
    } else if (idx < 200){
        int k    = idx - 160;
        int cell = k / 20;
        int rem  = k % 20;             // (jj-8)*10 + r*5 + p
        int jj = 8 + rem / 10;
        int r  = (rem % 10) / 5;
        int p  = rem % 5;
        int aj = 5*(1-r) + (jj-5);
        int d  = 5*r + p;
        const float* W = cell ? WhhA : WhhB;
        g_pack[(cell ? OFF_WHA89 : OFF_WHB89) + rem] = make_longlong2(
            (long long)pack2(0.5f*W[(      d)*HID + aj], 0.5f*W[(  HID+d)*HID + aj]),
            (long long)pack2(     W[(2*HID+d)*HID + aj], 0.5f*W[(3*HID+d)*HID + aj]));
    } else if (idx < 250){
        int k = idx - 200;
        int grp = k / 10;
        int rp  = k % 10;
        int r = rp / 5, p = rp % 5;
        int d = 5*r + p;
        longlong2 v;
        if (grp == 0){
            v = make_longlong2(
                (long long)pack2(0.5f*WihB[d],         0.5f*WihB[HID+d]),
                (long long)pack2(     WihB[2*HID+d],   0.5f*WihB[3*HID+d]));
        } else if (grp == 1){
            v = make_longlong2(
                (long long)pack2(0.5f*WihA[(      d)*2], 0.5f*WihA[(  HID+d)*2]),
                (long long)pack2(     WihA[(2*HID+d)*2], 0.5f*WihA[(3*HID+d)*2]));
        } else if (grp == 2){
            v = make_longlong2(
                (long long)pack2(0.5f*WihA[(      d)*2+1], 0.5f*WihA[(  HID+d)*2+1]),
                (long long)pack2(     WihA[(2*HID+d)*2+1], 0.5f*WihA[(3*HID+d)*2+1]));
        } else if (grp == 3){
            v = make_longlong2(
                (long long)pack2(0.5f*(bihB[d]       + bhhB[d]),
                                 0.5f*(bihB[HID+d]   + bhhB[HID+d])),
                (long long)pack2(     (bihB[2*HID+d] + bhhB[2*HID+d]),
                                 0.5f*(bihB[3*HID+d] + bhhB[3*HID+d])));
        } else {
            v = make_longlong2(
                (long long)pack2(0.5f*(bihA[d]       + bhhA[d]),
                                 0.5f*(bihA[HID+d]   + bhhA[HID+d])),
                (long long)pack2(     (bihA[2*HID+d] + bhhA[2*HID+d]),
                                 0.5f*(bihA[3*HID+d] + bhhA[3*HID+d])));
        }
        g_pack[idx] = v;
    }
}

// ---------- dual-port, split-thread, ILP-2 cell step ----------
// Each thread: 2 independent elements (E0, E1), owns dims rbase..rbase+4 of each.
// Every weight load (LDS/LDC) is applied to BOTH elements.
template<int NIN, int WH89, int WX1C>
__device__ __forceinline__ void cell_step(
    const longlong2* __restrict__ s_wh,   // 80 entries (jj=0..7)
    const longlong2* __restrict__ s_wx0,  // 10 entries
    const ull* bif, const ull* bgo,       // 5+5 ull, register-resident
    int rbase,
    float h0[5], float c0[5], float x00, float x01,
    float h1[5], float c1[5], float x10, float x11)
{
    // partner-h exchange for both chains, issued first (latency hiding)
    float hp0[5], hp1[5];
#pragma unroll
    for (int p = 0; p < 5; p++){
        hp0[p] = __shfl_xor_sync(0xffffffffu, h0[p], 1);
        hp1[p] = __shfl_xor_sync(0xffffffffu, h1[p], 1);
    }

    ull aIF0[5], aGO0[5], aIF1[5], aGO1[5];
#pragma unroll
    for (int p = 0; p < 5; p++){
        aIF0[p] = bif[p]; aGO0[p] = bgo[p];
        aIF1[p] = bif[p]; aGO1[p] = bgo[p];
    }

    // const-port rows jj = 8,9 (hp[3], hp[4]) — long-latency loads issued early
#pragma unroll
    for (int jj = 8; jj < 10; jj++){
        ull hb0 = bcast2(hp0[jj-5]);
        ull hb1 = bcast2(hp1[jj-5]);
#pragma unroll
        for (int p = 0; p < 5; p++){
            longlong2 w = c_w[WH89 + (jj-8)*10 + rbase + p];
            aIF0[p] = ffma2((ull)w.x, hb0, aIF0[p]);
            aGO0[p] = ffma2((ull)w.y, hb0, aGO0[p]);
            aIF1[p] = ffma2((ull)w.x, hb1, aIF1[p]);
            aGO1[p] = ffma2((ull)w.y, hb1, aGO1[p]);
        }
    }
    if (NIN == 2){
        ull xb0 = bcast2(x01);
        ull xb1 = bcast2(x11);
#pragma unroll
        for (int p = 0; p < 5; p++){
            longlong2 w = c_w[WX1C + rbase + p];
            aIF0[p] = ffma2((ull)w.x, xb0, aIF0[p]);
            aGO0[p] = ffma2((ull)w.y, xb0, aGO0[p]);
            aIF1[p] = ffma2((ull)w.x, xb1, aIF1[p]);
            aGO1[p] = ffma2((ull)w.y, xb1, aGO1[p]);
        }
    }
    // smem x0
    {
        ull xb0 = bcast2(x00);
        ull xb1 = bcast2(x10);
#pragma unroll
        for (int p = 0; p < 5; p++){
            longlong2 w = s_wx0[rbase + p];
            aIF0[p] = ffma2((ull)w.x, xb0, aIF0[p]);
            aGO0[p] = ffma2((ull)w.y, xb0, aGO0[p]);
            aIF1[p] = ffma2((ull)w.x, xb1, aIF1[p]);
            aGO1[p] = ffma2((ull)w.y, xb1, aGO1[p]);
        }
    }
    // smem own rows jj = 0..4
#pragma unroll
    for (int jj = 0; jj < 5; jj++){
        ull hb0 = bcast2(h0[jj]);
        ull hb1 = bcast2(h1[jj]);
#pragma unroll
        for (int p = 0; p < 5; p++){
            longlong2 w = s_wh[jj*10 + rbase + p];
            aIF0[p] = ffma2((ull)w.x, hb0, aIF0[p]);
            aGO0[p] = ffma2((ull)w.y, hb0, aGO0[p]);
            aIF1[p] = ffma2((ull)w.x, hb1, aIF1[p]);
            aGO1[p] = ffma2((ull)w.y, hb1, aGO1[p]);
        }
    }
    // smem partner rows jj = 5..7 (hp[0..2])
#pragma unroll
    for (int jj = 5; jj < 8; jj++){
        ull hb0 = bcast2(hp0[jj-5]);
        ull hb1 = bcast2(hp1[jj-5]);
#pragma unroll
        for (int p = 0; p < 5; p++){
            longlong2 w = s_wh[jj*10 + rbase + p];
            aIF0[p] = ffma2((ull)w.x, hb0, aIF0[p]);
            aGO0[p] = ffma2((ull)w.y, hb0, aGO0[p]);
            aIF1[p] = ffma2((ull)w.x, hb1, aIF1[p]);
            aGO1[p] = ffma2((ull)w.y, hb1, aGO1[p]);
        }
    }
    // epilogue: both chains, 5 MUFU per dim each
#pragma unroll
    for (int p = 0; p < 5; p++){
        float zi, zf, zg, zo;
        unpack2(aIF0[p], zi, zf);
        unpack2(aGO0[p], zg, zo);
        float si = fmaf(0.5f, tanh_ap(zi), 0.5f);
        float sf = fmaf(0.5f, tanh_ap(zf), 0.5f);
        float tg = tanh_ap(zg);
        float so = fmaf(0.5f, tanh_ap(zo), 0.5f);
        float cn = fmaf(sf, c0[p], si * tg);
        c0[p] = cn;
        h0[p] = so * tanh_ap(cn);
    }
#pragma unroll
    for (int p = 0; p < 5; p++){
        float zi, zf, zg, zo;
        unpack2(aIF1[p], zi, zf);
        unpack2(aGO1[p], zg, zo);
        float si = fmaf(0.5f, tanh_ap(zi), 0.5f);
        float sf = fmaf(0.5f, tanh_ap(zf), 0.5f);
        float tg = tanh_ap(zg);
        float so = fmaf(0.5f, tanh_ap(zo), 0.5f);
        float cn = fmaf(sf, c1[p], si * tg);
        c1[p] = cn;
        h1[p] = so * tanh_ap(cn);
    }
}

__global__ void __launch_bounds__(TPB, 1)
multicell_lstm_kernel(
    const float* __restrict__ x,
    const float* __restrict__ Wlin, const float* __restrict__ blin,
    float* __restrict__ out)
{
    // smem subset: [0..79] whB jj0-7, [80..159] whA jj0-7, [160..169] wxB, [170..179] wxA0
    __shared__ longlong2 s_w[180];
    const int tid = threadIdx.x;
    for (int i = tid; i < 180; i += TPB){
        int src;
        if      (i < 160) src = i;
        else if (i < 170) src = OFF_WXB  + (i - 160);
        else              src = OFF_WXA0 + (i - 170);
        s_w[i] = g_pack[src];
    }
    __syncthreads();

    const int rbase = (tid & 1) * 5;

    // register-resident biases
    ull bBif[5], bBgo[5], bAif[5], bAgo[5];
#pragma unroll
    for (int p = 0; p < 5; p++){
        longlong2 vb = c_w[OFF_BB + rbase + p];
        longlong2 va = c_w[OFF_BA + rbase + p];
        bBif[p] = (ull)vb.x; bBgo[p] = (ull)vb.y;
        bAif[p] = (ull)va.x; bAgo[p] = (ull)va.y;
    }

    // two elements per thread: e0 in [0,8192), e1 = e0 + 8192
    const int pi = (blockIdx.x * TPB + tid) >> 1;
    const int e0 = pi;
    const int e1 = pi + (BATCH / 2);
    const float4* xp0 = reinterpret_cast<const float4*>(x) + (size_t)e0 * TPAIRS;
    const float4* xp1 = reinterpret_cast<const float4*>(x) + (size_t)e1 * TPAIRS;

    float h0[5], c0[5], h1[5], c1[5];
#pragma unroll
    for (int p = 0; p < 5; p++){ h0[p]=0.f; c0[p]=0.f; h1[p]=0.f; c1[p]=0.f; }

    for (int p = 0; p < TPAIRS; p++){
        float4 xv0 = __ldg(&xp0[p]);
        float4 xv1 = __ldg(&xp1[p]);
        cell_step<1, OFF_WHB89, OFF_WXA1>(s_w,      s_w + 160, bBif, bBgo, rbase,
                                          h0, c0, xv0.x, 0.0f, h1, c1, xv1.x, 0.0f);
        cell_step<2, OFF_WHA89, OFF_WXA1>(s_w + 80, s_w + 170, bAif, bAgo, rbase,
                                          h0, c0, xv0.z, xv0.w, h1, c1, xv1.z, xv1.w);
    }

    // outputs: partial dot over owned dims + pair-sum, for both elements
    float a0 = 0.0f, a1 = 0.0f;
#pragma unroll
    for (int p = 0; p < 5; p++){
        float wl = __ldg(&Wlin[rbase + p]);
        a0 = fmaf(h0[p], wl, a0);
        a1 = fmaf(h1[p], wl, a1);
    }
    a0 += __shfl_xor_sync(0xffffffffu, a0, 1);
    a1 += __shfl_xor_sync(0xffffffffu, a1, 1);
    if ((tid & 1) == 0){
        float bl = __ldg(&blin[0]);
        out[e0] = fmaf(0.5f, tanh_ap(0.5f * (a0 + bl)), 0.5f);
        out[e1] = fmaf(0.5f, tanh_ap(0.5f * (a1 + bl)), 0.5f);
    }
}

extern "C" void kernel_launch(void* const* d_in, const int* in_sizes, int n_in,
                              void* d_out, int out_size)
{
    const float* x    = (const float*)d_in[0];
    const float* WihA = (const float*)d_in[1];
    const float* WhhA = (const float*)d_in[2];
    const float* bihA = (const float*)d_in[3];
    const float* bhhA = (const float*)d_in[4];
    const float* WihB = (const float*)d_in[5];
    const float* WhhB = (const float*)d_in[6];
    const float* bihB = (const float*)d_in[7];
    const float* bhhB = (const float*)d_in[8];
    const float* Wlin = (const float*)d_in[9];
    const float* blin = (const float*)d_in[10];
    float* out = (float*)d_out;

    pack_kernel<<<1, 256>>>(WihA, WhhA, bihA, bhhA, WihB, WhhB, bihB, bhhB);

    void* g_pack_dev = nullptr;
    cudaGetSymbolAddress(&g_pack_dev, g_pack);
    cudaMemcpyToSymbolAsync(c_w, g_pack_dev, 250 * sizeof(longlong2), 0,
                            cudaMemcpyDeviceToDevice, 0);

    // 2 threads/element x 2 elements/thread -> 16384 threads = 512 warps
    // = 1 warp/SMSP with ILP-2; weights loaded once per pair of elements.
    dim3 grid(BATCH / TPB), block(TPB);
    multicell_lstm_kernel<<<grid, block>>>(x, Wlin, blin, out);
}

// round 9
// speedup vs baseline: 1.0831x; 1.0831x over previous
#include <cuda_runtime.h>

typedef unsigned long long ull;

#define HID 10
#define BATCH 16384
#define TPAIRS 1024
#define TPB 256

// ---------- g_pack / c_w layout (250 longlong2) ----------
// entry(cell, jj, r, p): absolute j = (jj<5)? 5r+jj : 5(1-r)+(jj-5); dim d = 5r+p
//   = ( pack2(0.5*W[d][j], 0.5*W[10+d][j]), pack2(W[20+d][j], 0.5*W[30+d][j]) )
// [0..69]    whB jj=0..6 : jj*10 + r*5 + p      (smem)
// [70..139]  whA jj=0..6                        (smem)
// [140..169] whB jj=7..9 : (jj-7)*10 + r*5 + p  (const)
// [170..199] whA jj=7..9                        (const)
// [200..209] wxB  [r*5+p]                       (const -> regs)
// [210..219] wxA0                               (const -> regs)
// [220..229] wxA1                               (const)
// [230..239] bB  (bih+bhh fused)                (const -> regs)
// [240..249] bA                                 (const -> regs)
#define OFF_WHB   0
#define OFF_WHA   70
#define OFF_WHB79 140
#define OFF_WHA79 170
#define OFF_WXB   200
#define OFF_WXA0  210
#define OFF_WXA1  220
#define OFF_BB    230
#define OFF_BA    240

__constant__ longlong2 c_w[250];
__device__   longlong2 g_pack[250];

// ---------- packed fp32x2 helpers ----------
__device__ __forceinline__ ull pack2(float lo, float hi){
    ull r; asm("mov.b64 %0, {%1, %2};" : "=l"(r) : "f"(lo), "f"(hi)); return r;
}
__device__ __forceinline__ ull bcast2(float v){
    ull r; asm("mov.b64 %0, {%1, %1};" : "=l"(r) : "f"(v)); return r;
}
__device__ __forceinline__ void unpack2(ull v, float &lo, float &hi){
    asm("mov.b64 {%0, %1}, %2;" : "=f"(lo), "=f"(hi) : "l"(v));
}
__device__ __forceinline__ ull ffma2(ull a, ull b, ull c){
    ull d; asm("fma.rn.f32x2 %0, %1, %2, %3;" : "=l"(d) : "l"(a), "l"(b), "l"(c)); return d;
}
__device__ __forceinline__ float tanh_ap(float x){
    float r; asm("tanh.approx.f32 %0, %1;" : "=f"(r) : "f"(x)); return r;
}

// ---------- pack kernel ----------
__global__ void pack_kernel(
    const float* __restrict__ WihA, const float* __restrict__ WhhA,
    const float* __restrict__ bihA, const float* __restrict__ bhhA,
    const float* __restrict__ WihB, const float* __restrict__ WhhB,
    const float* __restrict__ bihB, const float* __restrict__ bhhB)
{
    int idx = threadIdx.x;
    if (idx < 140){
        // wh jj = 0..6 (smem region)
        int cell = idx / 70;           // 0 = B, 1 = A
        int rem  = idx % 70;           // jj*10 + r*5 + p
        int jj = rem / 10;
        int r  = (rem % 10) / 5;
        int p  = rem % 5;
        int aj = (jj < 5) ? (5*r + jj) : (5*(1-r) + (jj-5));
        int d  = 5*r + p;
        const float* W = cell ? WhhA : WhhB;
        g_pack[(cell ? OFF_WHA : OFF_WHB) + rem] = make_longlong2(
            (long long)pack2(0.5f*W[(      d)*HID + aj], 0.5f*W[(  HID+d)*HID + aj]),
            (long long)pack2(     W[(2*HID+d)*HID + aj], 0.5f*W[(3*HID+d)*HID + aj]));
    } else if (idx < 200){
        // wh jj = 7..9 (const region)
        int k    = idx - 140;
        int cell = k / 30;
        int rem  = k % 30;             // (jj-7)*10 + r*5 + p
        int jj = 7 + rem / 10;
        int r  = (rem % 10) / 5;
        int p  = rem % 5;
        int aj = 5*(1-r) + (jj-5);
        int d  = 5*r + p;
        const float* W = cell ? WhhA : WhhB;
        g_pack[(cell ? OFF_WHA79 : OFF_WHB79) + rem] = make_longlong2(
            (long long)pack2(0.5f*W[(      d)*HID + aj], 0.5f*W[(  HID+d)*HID + aj]),
            (long long)pack2(     W[(2*HID+d)*HID + aj], 0.5f*W[(3*HID+d)*HID + aj]));
    } else if (idx < 250){
        int k = idx - 200;
        int grp = k / 10;              // 0 wxB, 1 wxA0, 2 wxA1, 3 bB, 4 bA
        int rp  = k % 10;              // r*5 + p
        int r = rp / 5, p = rp % 5;
        int d = 5*r + p;
        longlong2 v;
        if (grp == 0){
            v = make_longlong2(
                (long long)pack2(0.5f*WihB[d],         0.5f*WihB[HID+d]),
                (long long)pack2(     WihB[2*HID+d],   0.5f*WihB[3*HID+d]));
        } else if (grp == 1){
            v = make_longlong2(
                (long long)pack2(0.5f*WihA[(      d)*2], 0.5f*WihA[(  HID+d)*2]),
                (long long)pack2(     WihA[(2*HID+d)*2], 0.5f*WihA[(3*HID+d)*2]));
        } else if (grp == 2){
            v = make_longlong2(
                (long long)pack2(0.5f*WihA[(      d)*2+1], 0.5f*WihA[(  HID+d)*2+1]),
                (long long)pack2(     WihA[(2*HID+d)*2+1], 0.5f*WihA[(3*HID+d)*2+1]));
        } else if (grp == 3){
            v = make_longlong2(
                (long long)pack2(0.5f*(bihB[d]       + bhhB[d]),
                                 0.5f*(bihB[HID+d]   + bhhB[HID+d])),
                (long long)pack2(     (bihB[2*HID+d] + bhhB[2*HID+d]),
                                 0.5f*(bihB[3*HID+d] + bhhB[3*HID+d])));
        } else {
            v = make_longlong2(
                (long long)pack2(0.5f*(bihA[d]       + bhhA[d]),
                                 0.5f*(bihA[HID+d]   + bhhA[HID+d])),
                (long long)pack2(     (bihA[2*HID+d] + bhhA[2*HID+d]),
                                 0.5f*(bihA[3*HID+d] + bhhA[3*HID+d])));
        }
        g_pack[idx] = v;
    }
}

// ---------- dual-port split-thread LSTM cell step ----------
// 2 threads/element; thread r owns dims rbase..rbase+4 (all 4 gates).
// smem:  h-rows jj=0..6 (s_wh, 70 entries)
// const: h-rows jj=7..9 + wxA1 (NIN==2)
// regs:  wx0 (wx0if/wx0go), biases (bif/bgo)
template<int NIN, int WH79, int WX1C>
__device__ __forceinline__ void cell_step(
    const longlong2* __restrict__ s_wh,
    const ull* wx0if, const ull* wx0go,
    const ull* bif, const ull* bgo,
    int rbase, float h[5], float c[5], float x0, float x1)
{
    // partner-h exchange first: shfl latency hides under subsequent matvec
    float hp[5];
#pragma unroll
    for (int p = 0; p < 5; p++) hp[p] = __shfl_xor_sync(0xffffffffu, h[p], 1);

    ull aIF[5], aGO[5];
#pragma unroll
    for (int p = 0; p < 5; p++){ aIF[p] = bif[p]; aGO[p] = bgo[p]; }

    // register-resident x0 contribution (no load)
    {
        ull xb = bcast2(x0);
#pragma unroll
        for (int p = 0; p < 5; p++){
            aIF[p] = ffma2(wx0if[p], xb, aIF[p]);
            aGO[p] = ffma2(wx0go[p], xb, aGO[p]);
        }
    }
    // const-port rows jj = 7,8,9 (hp[2..4]) — long-latency loads issued early
#pragma unroll
    for (int jj = 7; jj < 10; jj++){
        ull hb = bcast2(hp[jj-5]);
#pragma unroll
        for (int p = 0; p < 5; p++){
            longlong2 w = c_w[WH79 + (jj-7)*10 + rbase + p];
            aIF[p] = ffma2((ull)w.x, hb, aIF[p]);
            aGO[p] = ffma2((ull)w.y, hb, aGO[p]);
        }
    }
    if (NIN == 2){
        ull xb = bcast2(x1);
#pragma unroll
        for (int p = 0; p < 5; p++){
            longlong2 w = c_w[WX1C + rbase + p];
            aIF[p] = ffma2((ull)w.x, xb, aIF[p]);
            aGO[p] = ffma2((ull)w.y, xb, aGO[p]);
        }
    }
    // smem own rows jj = 0..4
#pragma unroll
    for (int jj = 0; jj < 5; jj++){
        ull hb = bcast2(h[jj]);
#pragma unroll
        for (int p = 0; p < 5; p++){
            longlong2 w = s_wh[jj*10 + rbase + p];
            aIF[p] = ffma2((ull)w.x, hb, aIF[p]);
            aGO[p] = ffma2((ull)w.y, hb, aGO[p]);
        }
    }
    // smem partner rows jj = 5,6 (hp[0..1])
#pragma unroll
    for (int jj = 5; jj < 7; jj++){
        ull hb = bcast2(hp[jj-5]);
#pragma unroll
        for (int p = 0; p < 5; p++){
            longlong2 w = s_wh[jj*10 + rbase + p];
            aIF[p] = ffma2((ull)w.x, hb, aIF[p]);
            aGO[p] = ffma2((ull)w.y, hb, aGO[p]);
        }
    }
    // epilogue: 5 MUFU per owned dim
#pragma unroll
    for (int p = 0; p < 5; p++){
        float zi, zf, zg, zo;
        unpack2(aIF[p], zi, zf);
        unpack2(aGO[p], zg, zo);
        float si = fmaf(0.5f, tanh_ap(zi), 0.5f);
        float sf = fmaf(0.5f, tanh_ap(zf), 0.5f);
        float tg = tanh_ap(zg);
        float so = fmaf(0.5f, tanh_ap(zo), 0.5f);
        float cn = fmaf(sf, c[p], si * tg);
        c[p] = cn;
        h[p] = so * tanh_ap(cn);
    }
}

__global__ void __launch_bounds__(TPB, 1)
multicell_lstm_kernel(
    const float* __restrict__ x,
    const float* __restrict__ Wlin, const float* __restrict__ blin,
    float* __restrict__ out)
{
    // smem subset: [0..69] whB jj0-6, [70..139] whA jj0-6
    __shared__ longlong2 s_w[140];
    const int tid = threadIdx.x;
    for (int i = tid; i < 140; i += TPB) s_w[i] = g_pack[i];
    __syncthreads();

    const int rbase = (tid & 1) * 5;

    // register-resident biases + wx weights (one-time divergent const reads)
    ull bBif[5], bBgo[5], bAif[5], bAgo[5];
    ull wxBif[5], wxBgo[5], wxA0if[5], wxA0go[5];
#pragma unroll
    for (int p = 0; p < 5; p++){
        longlong2 vb  = c_w[OFF_BB   + rbase + p];
        longlong2 va  = c_w[OFF_BA   + rbase + p];
        longlong2 vxb = c_w[OFF_WXB  + rbase + p];
        longlong2 vxa = c_w[OFF_WXA0 + rbase + p];
        bBif[p]  = (ull)vb.x;  bBgo[p]  = (ull)vb.y;
        bAif[p]  = (ull)va.x;  bAgo[p]  = (ull)va.y;
        wxBif[p] = (ull)vxb.x; wxBgo[p] = (ull)vxb.y;
        wxA0if[p]= (ull)vxa.x; wxA0go[p]= (ull)vxa.y;
    }

    const int e = (blockIdx.x * TPB + tid) >> 1;   // element id, 2 threads/element
    const float4* xp = reinterpret_cast<const float4*>(x) + (size_t)e * TPAIRS;

    float h[5], c[5];
#pragma unroll
    for (int p = 0; p < 5; p++){ h[p] = 0.0f; c[p] = 0.0f; }

    for (int p = 0; p < TPAIRS; p++){
        float4 xv = __ldg(&xp[p]);
        cell_step<1, OFF_WHB79, OFF_WXA1>(s_w,      wxBif,  wxBgo,  bBif, bBgo,
                                          rbase, h, c, xv.x, 0.0f);
        cell_step<2, OFF_WHA79, OFF_WXA1>(s_w + 70, wxA0if, wxA0go, bAif, bAgo,
                                          rbase, h, c, xv.z, xv.w);
    }

    // out = sigmoid(h @ Wlin.T + blin): partial dot over owned dims + pair-sum
    float a = 0.0f;
#pragma unroll
    for (int p = 0; p < 5; p++) a = fmaf(h[p], __ldg(&Wlin[rbase + p]), a);
    a += __shfl_xor_sync(0xffffffffu, a, 1);
    if ((tid & 1) == 0)
        out[e] = fmaf(0.5f, tanh_ap(0.5f * (a + __ldg(&blin[0]))), 0.5f);
}

extern "C" void kernel_launch(void* const* d_in, const int* in_sizes, int n_in,
                              void* d_out, int out_size)
{
    const float* x    = (const float*)d_in[0];
    const float* WihA = (const float*)d_in[1];
    const float* WhhA = (const float*)d_in[2];
    const float* bihA = (const float*)d_in[3];
    const float* bhhA = (const float*)d_in[4];
    const float* WihB = (const float*)d_in[5];
    const float* WhhB = (const float*)d_in[6];
    const float* bihB = (const float*)d_in[7];
    const float* bhhB = (const float*)d_in[8];
    const float* Wlin = (const float*)d_in[9];
    const float* blin = (const float*)d_in[10];
    float* out = (float*)d_out;

    pack_kernel<<<1, 256>>>(WihA, WhhA, bihA, bhhA, WihB, WhhB, bihB, bhhB);

    void* g_pack_dev = nullptr;
    cudaGetSymbolAddress(&g_pack_dev, g_pack);
    cudaMemcpyToSymbolAsync(c_w, g_pack_dev, 250 * sizeof(longlong2), 0,
                            cudaMemcpyDeviceToDevice, 0);

    // 2 threads/element, 2 warps/SMSP (r7 concurrency), lighter crossbar load
    dim3 grid((BATCH * 2) / TPB), block(TPB);
    multicell_lstm_kernel<<<grid, block>>>(x, Wlin, blin, out);
}

// round 10
// speedup vs baseline: 1.3234x; 1.2219x over previous
#include <cuda_runtime.h>

typedef unsigned long long ull;

#define HID 10
#define BATCH 16384
#define TPAIRS 1024
#define TPB 256

// ---------- g_pack / c_w layout (250 longlong2) ----------
// wh entry(cell, jj, r, p): absolute j = (jj<5)? 5r+jj : 5(1-r)+(jj-5); dim d = 5r+p
//   = ( pack2(0.5*W[d][j], 0.5*W[10+d][j]), pack2(W[20+d][j], 0.5*W[30+d][j]) )
// [0..99]    whB jj=0..9 : jj*10 + r*5 + p      (smem)
// [100..199] whA jj=0..9                        (smem)
// [200..209] wxB  [r*5+p]                       (const -> regs, prologue)
// [210..219] wxA0                               (const -> regs, prologue)
// [220..229] wxA1                               (const -> regs, prologue)
// [230..239] bB  (bih+bhh fused)                (const -> regs, prologue)
// [240..249] bA                                 (const -> regs, prologue)
#define OFF_WHB   0
#define OFF_WHA   100
#define OFF_WXB   200
#define OFF_WXA0  210
#define OFF_WXA1  220
#define OFF_BB    230
#define OFF_BA    240

__constant__ longlong2 c_w[250];
__device__   longlong2 g_pack[250];

// ---------- packed fp32x2 helpers ----------
__device__ __forceinline__ ull pack2(float lo, float hi){
    ull r; asm("mov.b64 %0, {%1, %2};" : "=l"(r) : "f"(lo), "f"(hi)); return r;
}
__device__ __forceinline__ ull bcast2(float v){
    ull r; asm("mov.b64 %0, {%1, %1};" : "=l"(r) : "f"(v)); return r;
}
__device__ __forceinline__ void unpack2(ull v, float &lo, float &hi){
    asm("mov.b64 {%0, %1}, %2;" : "=f"(lo), "=f"(hi) : "l"(v));
}
__device__ __forceinline__ ull ffma2(ull a, ull b, ull c){
    ull d; asm("fma.rn.f32x2 %0, %1, %2, %3;" : "=l"(d) : "l"(a), "l"(b), "l"(c)); return d;
}
__device__ __forceinline__ float tanh_ap(float x){
    float r; asm("tanh.approx.f32 %0, %1;" : "=f"(r) : "f"(x)); return r;
}

// ---------- pack kernel ----------
__global__ void pack_kernel(
    const float* __restrict__ WihA, const float* __restrict__ WhhA,
    const float* __restrict__ bihA, const float* __restrict__ bhhA,
    const float* __restrict__ WihB, const float* __restrict__ WhhB,
    const float* __restrict__ bihB, const float* __restrict__ bhhB)
{
    int idx = threadIdx.x;
    if (idx < 200){
        // wh jj = 0..9, both cells
        int cell = idx / 100;          // 0 = B, 1 = A
        int rem  = idx % 100;          // jj*10 + r*5 + p
        int jj = rem / 10;
        int r  = (rem % 10) / 5;
        int p  = rem % 5;
        int aj = (jj < 5) ? (5*r + jj) : (5*(1-r) + (jj-5));
        int d  = 5*r + p;
        const float* W = cell ? WhhA : WhhB;
        g_pack[(cell ? OFF_WHA : OFF_WHB) + rem] = make_longlong2(
            (long long)pack2(0.5f*W[(      d)*HID + aj], 0.5f*W[(  HID+d)*HID + aj]),
            (long long)pack2(     W[(2*HID+d)*HID + aj], 0.5f*W[(3*HID+d)*HID + aj]));
    } else if (idx < 250){
        int k = idx - 200;
        int grp = k / 10;              // 0 wxB, 1 wxA0, 2 wxA1, 3 bB, 4 bA
        int rp  = k % 10;              // r*5 + p
        int r = rp / 5, p = rp % 5;
        int d = 5*r + p;
        longlong2 v;
        if (grp == 0){
            v = make_longlong2(
                (long long)pack2(0.5f*WihB[d],         0.5f*WihB[HID+d]),
                (long long)pack2(     WihB[2*HID+d],   0.5f*WihB[3*HID+d]));
        } else if (grp == 1){
            v = make_longlong2(
                (long long)pack2(0.5f*WihA[(      d)*2], 0.5f*WihA[(  HID+d)*2]),
                (long long)pack2(     WihA[(2*HID+d)*2], 0.5f*WihA[(3*HID+d)*2]));
        } else if (grp == 2){
            v = make_longlong2(
                (long long)pack2(0.5f*WihA[(      d)*2+1], 0.5f*WihA[(  HID+d)*2+1]),
                (long long)pack2(     WihA[(2*HID+d)*2+1], 0.5f*WihA[(3*HID+d)*2+1]));
        } else if (grp == 3){
            v = make_longlong2(
                (long long)pack2(0.5f*(bihB[d]       + bhhB[d]),
                                 0.5f*(bihB[HID+d]   + bhhB[HID+d])),
                (long long)pack2(     (bihB[2*HID+d] + bhhB[2*HID+d]),
                                 0.5f*(bihB[3*HID+d] + bhhB[3*HID+d])));
        } else {
            v = make_longlong2(
                (long long)pack2(0.5f*(bihA[d]       + bhhA[d]),
                                 0.5f*(bihA[HID+d]   + bhhA[HID+d])),
                (long long)pack2(     (bihA[2*HID+d] + bhhA[2*HID+d]),
                                 0.5f*(bihA[3*HID+d] + bhhA[3*HID+d])));
        }
        g_pack[idx] = v;
    }
}

// ---------- pure smem+reg LSTM cell step ----------
// 2 threads/element; thread r owns dims rbase..rbase+4 (all 4 gates).
// smem: ALL h-rows jj=0..9 (s_wh, 100 entries). regs: wx, bias. No LDC in loop.
template<int NIN>
__device__ __forceinline__ void cell_step(
    const longlong2* __restrict__ s_wh,
    const ull* wx0if, const ull* wx0go,
    const ull* wx1if, const ull* wx1go,
    const ull* bif, const ull* bgo,
    int rbase, float h[5], float c[5], float x0, float x1)
{
    // partner-h exchange first: shfl latency hides under own-row matvec
    float hp[5];
#pragma unroll
    for (int p = 0; p < 5; p++) hp[p] = __shfl_xor_sync(0xffffffffu, h[p], 1);

    ull aIF[5], aGO[5];
#pragma unroll
    for (int p = 0; p < 5; p++){ aIF[p] = bif[p]; aGO[p] = bgo[p]; }

    // register-resident x contributions (no loads)
    {
        ull xb = bcast2(x0);
#pragma unroll
        for (int p = 0; p < 5; p++){
            aIF[p] = ffma2(wx0if[p], xb, aIF[p]);
            aGO[p] = ffma2(wx0go[p], xb, aGO[p]);
        }
    }
    if (NIN == 2){
        ull xb = bcast2(x1);
#pragma unroll
        for (int p = 0; p < 5; p++){
            aIF[p] = ffma2(wx1if[p], xb, aIF[p]);
            aGO[p] = ffma2(wx1go[p], xb, aGO[p]);
        }
    }
    // smem own rows jj = 0..4 (h known immediately)
#pragma unroll
    for (int jj = 0; jj < 5; jj++){
        ull hb = bcast2(h[jj]);
#pragma unroll
        for (int p = 0; p < 5; p++){
            longlong2 w = s_wh[jj*10 + rbase + p];
            aIF[p] = ffma2((ull)w.x, hb, aIF[p]);
            aGO[p] = ffma2((ull)w.y, hb, aGO[p]);
        }
    }
    // smem partner rows jj = 5..9 (hp ready by now)
#pragma unroll
    for (int jj = 5; jj < 10; jj++){
        ull hb = bcast2(hp[jj-5]);
#pragma unroll
        for (int p = 0; p < 5; p++){
            longlong2 w = s_wh[jj*10 + rbase + p];
            aIF[p] = ffma2((ull)w.x, hb, aIF[p]);
            aGO[p] = ffma2((ull)w.y, hb, aGO[p]);
        }
    }
    // epilogue: 5 MUFU per owned dim
#pragma unroll
    for (int p = 0; p < 5; p++){
        float zi, zf, zg, zo;
        unpack2(aIF[p], zi, zf);
        unpack2(aGO[p], zg, zo);
        float si = fmaf(0.5f, tanh_ap(zi), 0.5f);
        float sf = fmaf(0.5f, tanh_ap(zf), 0.5f);
        float tg = tanh_ap(zg);
        float so = fmaf(0.5f, tanh_ap(zo), 0.5f);
        float cn = fmaf(sf, c[p], si * tg);
        c[p] = cn;
        h[p] = so * tanh_ap(cn);
    }
}

__global__ void __launch_bounds__(TPB, 1)
multicell_lstm_kernel(
    const float* __restrict__ x,
    const float* __restrict__ Wlin, const float* __restrict__ blin,
    float* __restrict__ out)
{
    // all recurrent weights in smem: [0..99] whB, [100..199] whA
    __shared__ longlong2 s_w[200];
    const int tid = threadIdx.x;
    for (int i = tid; i < 200; i += TPB) s_w[i] = g_pack[i];
    __syncthreads();

    const int rbase = (tid & 1) * 5;

    // one-time divergent const reads -> registers (loop-invariant)
    ull bBif[5], bBgo[5], bAif[5], bAgo[5];
    ull wxBif[5], wxBgo[5], wxA0if[5], wxA0go[5], wxA1if[5], wxA1go[5];
#pragma unroll
    for (int p = 0; p < 5; p++){
        longlong2 vb   = c_w[OFF_BB   + rbase + p];
        longlong2 va   = c_w[OFF_BA   + rbase + p];
        longlong2 vxb  = c_w[OFF_WXB  + rbase + p];
        longlong2 vxa0 = c_w[OFF_WXA0 + rbase + p];
        longlong2 vxa1 = c_w[OFF_WXA1 + rbase + p];
        bBif[p]   = (ull)vb.x;   bBgo[p]   = (ull)vb.y;
        bAif[p]   = (ull)va.x;   bAgo[p]   = (ull)va.y;
        wxBif[p]  = (ull)vxb.x;  wxBgo[p]  = (ull)vxb.y;
        wxA0if[p] = (ull)vxa0.x; wxA0go[p] = (ull)vxa0.y;
        wxA1if[p] = (ull)vxa1.x; wxA1go[p] = (ull)vxa1.y;
    }

    const int e = (blockIdx.x * TPB + tid) >> 1;   // element id, 2 threads/element
    const float4* xp = reinterpret_cast<const float4*>(x) + (size_t)e * TPAIRS;

    float h[5], c[5];
#pragma unroll
    for (int p = 0; p < 5; p++){ h[p] = 0.0f; c[p] = 0.0f; }

    for (int p = 0; p < TPAIRS; p++){
        float4 xv = __ldg(&xp[p]);
        cell_step<1>(s_w,       wxBif,  wxBgo,  wxBif,  wxBgo,  bBif, bBgo,
                     rbase, h, c, xv.x, 0.0f);
        cell_step<2>(s_w + 100, wxA0if, wxA0go, wxA1if, wxA1go, bAif, bAgo,
                     rbase, h, c, xv.z, xv.w);
    }

    // out = sigmoid(h @ Wlin.T + blin): partial dot over owned dims + pair-sum
    float a = 0.0f;
#pragma unroll
    for (int p = 0; p < 5; p++) a = fmaf(h[p], __ldg(&Wlin[rbase + p]), a);
    a += __shfl_xor_sync(0xffffffffu, a, 1);
    if ((tid & 1) == 0)
        out[e] = fmaf(0.5f, tanh_ap(0.5f * (a + __ldg(&blin[0]))), 0.5f);
}

extern "C" void kernel_launch(void* const* d_in, const int* in_sizes, int n_in,
                              void* d_out, int out_size)
{
    const float* x    = (const float*)d_in[0];
    const float* WihA = (const float*)d_in[1];
    const float* WhhA = (const float*)d_in[2];
    const float* bihA = (const float*)d_in[3];
    const float* bhhA = (const float*)d_in[4];
    const float* WihB = (const float*)d_in[5];
    const float* WhhB = (const float*)d_in[6];
    const float* bihB = (const float*)d_in[7];
    const float* bhhB = (const float*)d_in[8];
    const float* Wlin = (const float*)d_in[9];
    const float* blin = (const float*)d_in[10];
    float* out = (float*)d_out;

    pack_kernel<<<1, 256>>>(WihA, WhhA, bihA, bhhA, WihB, WhhB, bihB, bhhB);

    void* g_pack_dev = nullptr;
    cudaGetSymbolAddress(&g_pack_dev, g_pack);
    cudaMemcpyToSymbolAsync(c_w, g_pack_dev, 250 * sizeof(longlong2), 0,
                            cudaMemcpyDeviceToDevice, 0);

    // 2 threads/element, 2 warps/SMSP; hot loop = smem + regs only (zero LDC)
    dim3 grid((BATCH * 2) / TPB), block(TPB);
    multicell_lstm_kernel<<<grid, block>>>(x, Wlin, blin, out);
}

// round 11
// speedup vs baseline: 1.3855x; 1.0469x over previous
#include <cuda_runtime.h>

typedef unsigned long long ull;

#define HID 10
#define BATCH 16384
#define TPAIRS 1024
#define TPB 256

// ---------- g_pack / c_w layout (250 longlong2), identical to r10 ----------
#define OFF_WHB   0
#define OFF_WHA   100
#define OFF_WXB   200
#define OFF_WXA0  210
#define OFF_WXA1  220
#define OFF_BB    230
#define OFF_BA    240

__constant__ longlong2 c_w[250];
__device__   longlong2 g_pack[250];

// ---------- packed fp32x2 helpers ----------
__device__ __forceinline__ ull pack2(float lo, float hi){
    ull r; asm("mov.b64 %0, {%1, %2};" : "=l"(r) : "f"(lo), "f"(hi)); return r;
}
__device__ __forceinline__ ull bcast2(float v){
    ull r; asm("mov.b64 %0, {%1, %1};" : "=l"(r) : "f"(v)); return r;
}
__device__ __forceinline__ void unpack2(ull v, float &lo, float &hi){
    asm("mov.b64 {%0, %1}, %2;" : "=f"(lo), "=f"(hi) : "l"(v));
}
__device__ __forceinline__ ull ffma2(ull a, ull b, ull c){
    ull d; asm("fma.rn.f32x2 %0, %1, %2, %3;" : "=l"(d) : "l"(a), "l"(b), "l"(c)); return d;
}
__device__ __forceinline__ float tanh_ap(float x){
    float r; asm("tanh.approx.f32 %0, %1;" : "=f"(r) : "f"(x)); return r;
}

// ---------- pack kernel (identical to r10, known-good) ----------
__global__ void pack_kernel(
    const float* __restrict__ WihA, const float* __restrict__ WhhA,
    const float* __restrict__ bihA, const float* __restrict__ bhhA,
    const float* __restrict__ WihB, const float* __restrict__ WhhB,
    const float* __restrict__ bihB, const float* __restrict__ bhhB)
{
    int idx = threadIdx.x;
    if (idx < 200){
        int cell = idx / 100;          // 0 = B, 1 = A
        int rem  = idx % 100;          // jj*10 + r*5 + p
        int jj = rem / 10;
        int r  = (rem % 10) / 5;
        int p  = rem % 5;
        int aj = (jj < 5) ? (5*r + jj) : (5*(1-r) + (jj-5));
        int d  = 5*r + p;
        const float* W = cell ? WhhA : WhhB;
        g_pack[(cell ? OFF_WHA : OFF_WHB) + rem] = make_longlong2(
            (long long)pack2(0.5f*W[(      d)*HID + aj], 0.5f*W[(  HID+d)*HID + aj]),
            (long long)pack2(     W[(2*HID+d)*HID + aj], 0.5f*W[(3*HID+d)*HID + aj]));
    } else if (idx < 250){
        int k = idx - 200;
        int grp = k / 10;              // 0 wxB, 1 wxA0, 2 wxA1, 3 bB, 4 bA
        int rp  = k % 10;              // r*5 + p
        int r = rp / 5, p = rp % 5;
        int d = 5*r + p;
        longlong2 v;
        if (grp == 0){
            v = make_longlong2(
                (long long)pack2(0.5f*WihB[d],         0.5f*WihB[HID+d]),
                (long long)pack2(     WihB[2*HID+d],   0.5f*WihB[3*HID+d]));
        } else if (grp == 1){
            v = make_longlong2(
                (long long)pack2(0.5f*WihA[(      d)*2], 0.5f*WihA[(  HID+d)*2]),
                (long long)pack2(     WihA[(2*HID+d)*2], 0.5f*WihA[(3*HID+d)*2]));
        } else if (grp == 2){
            v = make_longlong2(
                (long long)pack2(0.5f*WihA[(      d)*2+1], 0.5f*WihA[(  HID+d)*2+1]),
                (long long)pack2(     WihA[(2*HID+d)*2+1], 0.5f*WihA[(3*HID+d)*2+1]));
        } else if (grp == 3){
            v = make_longlong2(
                (long long)pack2(0.5f*(bihB[d]       + bhhB[d]),
                                 0.5f*(bihB[HID+d]   + bhhB[HID+d])),
                (long long)pack2(     (bihB[2*HID+d] + bhhB[2*HID+d]),
                                 0.5f*(bihB[3*HID+d] + bhhB[3*HID+d])));
        } else {
            v = make_longlong2(
                (long long)pack2(0.5f*(bihA[d]       + bhhA[d]),
                                 0.5f*(bihA[HID+d]   + bhhA[HID+d])),
                (long long)pack2(     (bihA[2*HID+d] + bhhA[2*HID+d]),
                                 0.5f*(bihA[3*HID+d] + bhhA[3*HID+d])));
        }
        g_pack[idx] = v;
    }
}

// ---------- pure smem+reg LSTM cell step, x-term LAST (LDG latency cover) ----------
template<int NIN>
__device__ __forceinline__ void cell_step(
    const longlong2* __restrict__ s_wh,
    const ull* wx0if, const ull* wx0go,
    const ull* wx1if, const ull* wx1go,
    const ull* bif, const ull* bgo,
    int rbase, float h[5], float c[5], float x0, float x1)
{
    // partner-h exchange first: shfl latency hides under own-row matvec
    float hp[5];
#pragma unroll
    for (int p = 0; p < 5; p++) hp[p] = __shfl_xor_sync(0xffffffffu, h[p], 1);

    ull aIF[5], aGO[5];
#pragma unroll
    for (int p = 0; p < 5; p++){ aIF[p] = bif[p]; aGO[p] = bgo[p]; }

    // smem own rows jj = 0..4 (h known immediately)
#pragma unroll
    for (int jj = 0; jj < 5; jj++){
        ull hb = bcast2(h[jj]);
#pragma unroll
        for (int p = 0; p < 5; p++){
            longlong2 w = s_wh[jj*10 + rbase + p];
            aIF[p] = ffma2((ull)w.x, hb, aIF[p]);
            aGO[p] = ffma2((ull)w.y, hb, aGO[p]);
        }
    }
    // smem partner rows jj = 5..9 (hp ready by now)
#pragma unroll
    for (int jj = 5; jj < 10; jj++){
        ull hb = bcast2(hp[jj-5]);
#pragma unroll
        for (int p = 0; p < 5; p++){
            longlong2 w = s_wh[jj*10 + rbase + p];
            aIF[p] = ffma2((ull)w.x, hb, aIF[p]);
            aGO[p] = ffma2((ull)w.y, hb, aGO[p]);
        }
    }
    // x contributions LAST: ~400 cyc of matvec above covers the x LDG latency
    {
        ull xb = bcast2(x0);
#pragma unroll
        for (int p = 0; p < 5; p++){
            aIF[p] = ffma2(wx0if[p], xb, aIF[p]);
            aGO[p] = ffma2(wx0go[p], xb, aGO[p]);
        }
    }
    if (NIN == 2){
        ull xb = bcast2(x1);
#pragma unroll
        for (int p = 0; p < 5; p++){
            aIF[p] = ffma2(wx1if[p], xb, aIF[p]);
            aGO[p] = ffma2(wx1go[p], xb, aGO[p]);
        }
    }
    // epilogue: 5 MUFU per owned dim
#pragma unroll
    for (int p = 0; p < 5; p++){
        float zi, zf, zg, zo;
        unpack2(aIF[p], zi, zf);
        unpack2(aGO[p], zg, zo);
        float si = fmaf(0.5f, tanh_ap(zi), 0.5f);
        float sf = fmaf(0.5f, tanh_ap(zf), 0.5f);
        float tg = tanh_ap(zg);
        float so = fmaf(0.5f, tanh_ap(zo), 0.5f);
        float cn = fmaf(sf, c[p], si * tg);
        c[p] = cn;
        h[p] = so * tanh_ap(cn);
    }
}

__global__ void __launch_bounds__(TPB, 1)
multicell_lstm_kernel(
    const float* __restrict__ x,
    const float* __restrict__ Wlin, const float* __restrict__ blin,
    float* __restrict__ out)
{
    // all recurrent weights in smem: [0..99] whB, [100..199] whA
    __shared__ longlong2 s_w[200];
    const int tid = threadIdx.x;
    for (int i = tid; i < 200; i += TPB) s_w[i] = g_pack[i];
    __syncthreads();

    const int rbase = (tid & 1) * 5;

    // one-time divergent const reads -> registers (loop-invariant)
    ull bBif[5], bBgo[5], bAif[5], bAgo[5];
    ull wxBif[5], wxBgo[5], wxA0if[5], wxA0go[5], wxA1if[5], wxA1go[5];
#pragma unroll
    for (int p = 0; p < 5; p++){
        longlong2 vb   = c_w[OFF_BB   + rbase + p];
        longlong2 va   = c_w[OFF_BA   + rbase + p];
        longlong2 vxb  = c_w[OFF_WXB  + rbase + p];
        longlong2 vxa0 = c_w[OFF_WXA0 + rbase + p];
        longlong2 vxa1 = c_w[OFF_WXA1 + rbase + p];
        bBif[p]   = (ull)vb.x;   bBgo[p]   = (ull)vb.y;
        bAif[p]   = (ull)va.x;   bAgo[p]   = (ull)va.y;
        wxBif[p]  = (ull)vxb.x;  wxBgo[p]  = (ull)vxb.y;
        wxA0if[p] = (ull)vxa0.x; wxA0go[p] = (ull)vxa0.y;
        wxA1if[p] = (ull)vxa1.x; wxA1go[p] = (ull)vxa1.y;
    }

    const int e = (blockIdx.x * TPB + tid) >> 1;   // element id, 2 threads/element
    const float4* xp = reinterpret_cast<const float4*>(x) + (size_t)e * TPAIRS;

    float h[5], c[5];
#pragma unroll
    for (int p = 0; p < 5; p++){ h[p] = 0.0f; c[p] = 0.0f; }

    // software prefetch: xv holds step p's data, loaded one iteration ahead
    float4 xv = __ldg(&xp[0]);
    for (int p = 0; p < TPAIRS; p++){
        float4 xnext = __ldg(&xp[(p + 1) & (TPAIRS - 1)]);  // wrap: harmless reload of [0]
        cell_step<1>(s_w,       wxBif,  wxBgo,  wxBif,  wxBgo,  bBif, bBgo,
                     rbase, h, c, xv.x, 0.0f);
        cell_step<2>(s_w + 100, wxA0if, wxA0go, wxA1if, wxA1go, bAif, bAgo,
                     rbase, h, c, xv.z, xv.w);
        xv = xnext;
    }

    // out = sigmoid(h @ Wlin.T + blin): partial dot over owned dims + pair-sum
    float a = 0.0f;
#pragma unroll
    for (int p = 0; p < 5; p++) a = fmaf(h[p], __ldg(&Wlin[rbase + p]), a);
    a += __shfl_xor_sync(0xffffffffu, a, 1);
    if ((tid & 1) == 0)
        out[e] = fmaf(0.5f, tanh_ap(0.5f * (a + __ldg(&blin[0]))), 0.5f);
}

extern "C" void kernel_launch(void* const* d_in, const int* in_sizes, int n_in,
                              void* d_out, int out_size)
{
    const float* x    = (const float*)d_in[0];
    const float* WihA = (const float*)d_in[1];
    const float* WhhA = (const float*)d_in[2];
    const float* bihA = (const float*)d_in[3];
    const float* bhhA = (const float*)d_in[4];
    const float* WihB = (const float*)d_in[5];
    const float* WhhB = (const float*)d_in[6];
    const float* bihB = (const float*)d_in[7];
    const float* bhhB = (const float*)d_in[8];
    const float* Wlin = (const float*)d_in[9];
    const float* blin = (const float*)d_in[10];
    float* out = (float*)d_out;

    pack_kernel<<<1, 256>>>(WihA, WhhA, bihA, bhhA, WihB, WhhB, bihB, bhhB);

    void* g_pack_dev = nullptr;
    cudaGetSymbolAddress(&g_pack_dev, g_pack);
    cudaMemcpyToSymbolAsync(c_w, g_pack_dev, 250 * sizeof(longlong2), 0,
                            cudaMemcpyDeviceToDevice, 0);

    // 2 threads/element, 2 warps/SMSP; smem+regs loop with x prefetch
    dim3 grid((BATCH * 2) / TPB), block(TPB);
    multicell_lstm_kernel<<<grid, block>>>(x, Wlin, blin, out);
}

// round 12
// speedup vs baseline: 1.4311x; 1.0330x over previous
#include <cuda_runtime.h>

typedef unsigned long long ull;

#define HID 10
#define BATCH 16384
#define TPAIRS 1024
#define TPB 224
#define NBLK 148

// ---------- g_pack / c_w layout (250 longlong2), identical to r10/r11 ----------
#define OFF_WHB   0
#define OFF_WHA   100
#define OFF_WXB   200
#define OFF_WXA0  210
#define OFF_WXA1  220
#define OFF_BB    230
#define OFF_BA    240

__constant__ longlong2 c_w[250];
__device__   longlong2 g_pack[250];

// ---------- packed fp32x2 helpers ----------
__device__ __forceinline__ ull pack2(float lo, float hi){
    ull r; asm("mov.b64 %0, {%1, %2};" : "=l"(r) : "f"(lo), "f"(hi)); return r;
}
__device__ __forceinline__ ull bcast2(float v){
    ull r; asm("mov.b64 %0, {%1, %1};" : "=l"(r) : "f"(v)); return r;
}
__device__ __forceinline__ void unpack2(ull v, float &lo, float &hi){
    asm("mov.b64 {%0, %1}, %2;" : "=f"(lo), "=f"(hi) : "l"(v));
}
__device__ __forceinline__ ull ffma2(ull a, ull b, ull c){
    ull d; asm("fma.rn.f32x2 %0, %1, %2, %3;" : "=l"(d) : "l"(a), "l"(b), "l"(c)); return d;
}
__device__ __forceinline__ float tanh_ap(float x){
    float r; asm("tanh.approx.f32 %0, %1;" : "=f"(r) : "f"(x)); return r;
}

// ---------- pack kernel (identical to r10/r11, known-good) ----------
__global__ void pack_kernel(
    const float* __restrict__ WihA, const float* __restrict__ WhhA,
    const float* __restrict__ bihA, const float* __restrict__ bhhA,
    const float* __restrict__ WihB, const float* __restrict__ WhhB,
    const float* __restrict__ bihB, const float* __restrict__ bhhB)
{
    int idx = threadIdx.x;
    if (idx < 200){
        int cell = idx / 100;          // 0 = B, 1 = A
        int rem  = idx % 100;          // jj*10 + r*5 + p
        int jj = rem / 10;
        int r  = (rem % 10) / 5;
        int p  = rem % 5;
        int aj = (jj < 5) ? (5*r + jj) : (5*(1-r) + (jj-5));
        int d  = 5*r + p;
        const float* W = cell ? WhhA : WhhB;
        g_pack[(cell ? OFF_WHA : OFF_WHB) + rem] = make_longlong2(
            (long long)pack2(0.5f*W[(      d)*HID + aj], 0.5f*W[(  HID+d)*HID + aj]),
            (long long)pack2(     W[(2*HID+d)*HID + aj], 0.5f*W[(3*HID+d)*HID + aj]));
    } else if (idx < 250){
        int k = idx - 200;
        int grp = k / 10;              // 0 wxB, 1 wxA0, 2 wxA1, 3 bB, 4 bA
        int rp  = k % 10;              // r*5 + p
        int r = rp / 5, p = rp % 5;
        int d = 5*r + p;
        longlong2 v;
        if (grp == 0){
            v = make_longlong2(
                (long long)pack2(0.5f*WihB[d],         0.5f*WihB[HID+d]),
                (long long)pack2(     WihB[2*HID+d],   0.5f*WihB[3*HID+d]));
        } else if (grp == 1){
            v = make_longlong2(
                (long long)pack2(0.5f*WihA[(      d)*2], 0.5f*WihA[(  HID+d)*2]),
                (long long)pack2(     WihA[(2*HID+d)*2], 0.5f*WihA[(3*HID+d)*2]));
        } else if (grp == 2){
            v = make_longlong2(
                (long long)pack2(0.5f*WihA[(      d)*2+1], 0.5f*WihA[(  HID+d)*2+1]),
                (long long)pack2(     WihA[(2*HID+d)*2+1], 0.5f*WihA[(3*HID+d)*2+1]));
        } else if (grp == 3){
            v = make_longlong2(
                (long long)pack2(0.5f*(bihB[d]       + bhhB[d]),
                                 0.5f*(bihB[HID+d]   + bhhB[HID+d])),
                (long long)pack2(     (bihB[2*HID+d] + bhhB[2*HID+d]),
                                 0.5f*(bihB[3*HID+d] + bhhB[3*HID+d])));
        } else {
            v = make_longlong2(
                (long long)pack2(0.5f*(bihA[d]       + bhhA[d]),
                                 0.5f*(bihA[HID+d]   + bhhA[HID+d])),
                (long long)pack2(     (bihA[2*HID+d] + bhhA[2*HID+d]),
                                 0.5f*(bihA[3*HID+d] + bhhA[3*HID+d])));
        }
        g_pack[idx] = v;
    }
}

// ---------- pure smem+reg LSTM cell step; optional register-resident jj=0 row ----------
template<int NIN, bool R0>
__device__ __forceinline__ void cell_step(
    const longlong2* __restrict__ s_wh,
    const ull* w0if, const ull* w0go,     // own jj=0 row (used iff R0)
    const ull* wx0if, const ull* wx0go,
    const ull* wx1if, const ull* wx1go,
    const ull* bif, const ull* bgo,
    int rbase, float h[5], float c[5], float x0, float x1)
{
    // partner-h exchange first: shfl latency hides under own-row matvec
    float hp[5];
#pragma unroll
    for (int p = 0; p < 5; p++) hp[p] = __shfl_xor_sync(0xffffffffu, h[p], 1);

    ull aIF[5], aGO[5];
#pragma unroll
    for (int p = 0; p < 5; p++){ aIF[p] = bif[p]; aGO[p] = bgo[p]; }

    // own jj=0 row from registers (no load)
    if (R0){
        ull hb = bcast2(h[0]);
#pragma unroll
        for (int p = 0; p < 5; p++){
            aIF[p] = ffma2(w0if[p], hb, aIF[p]);
            aGO[p] = ffma2(w0go[p], hb, aGO[p]);
        }
    }
    // smem own rows
#pragma unroll
    for (int jj = (R0 ? 1 : 0); jj < 5; jj++){
        ull hb = bcast2(h[jj]);
#pragma unroll
        for (int p = 0; p < 5; p++){
            longlong2 w = s_wh[jj*10 + rbase + p];
            aIF[p] = ffma2((ull)w.x, hb, aIF[p]);
            aGO[p] = ffma2((ull)w.y, hb, aGO[p]);
        }
    }
    // smem partner rows jj = 5..9 (hp ready by now)
#pragma unroll
    for (int jj = 5; jj < 10; jj++){
        ull hb = bcast2(hp[jj-5]);
#pragma unroll
        for (int p = 0; p < 5; p++){
            longlong2 w = s_wh[jj*10 + rbase + p];
            aIF[p] = ffma2((ull)w.x, hb, aIF[p]);
            aGO[p] = ffma2((ull)w.y, hb, aGO[p]);
        }
    }
    // x contributions LAST: matvec above covers the x LDG latency
    {
        ull xb = bcast2(x0);
#pragma unroll
        for (int p = 0; p < 5; p++){
            aIF[p] = ffma2(wx0if[p], xb, aIF[p]);
            aGO[p] = ffma2(wx0go[p], xb, aGO[p]);
        }
    }
    if (NIN == 2){
        ull xb = bcast2(x1);
#pragma unroll
        for (int p = 0; p < 5; p++){
            aIF[p] = ffma2(wx1if[p], xb, aIF[p]);
            aGO[p] = ffma2(wx1go[p], xb, aGO[p]);
        }
    }
    // epilogue: 5 MUFU per owned dim
#pragma unroll
    for (int p = 0; p < 5; p++){
        float zi, zf, zg, zo;
        unpack2(aIF[p], zi, zf);
        unpack2(aGO[p], zg, zo);
        float si = fmaf(0.5f, tanh_ap(zi), 0.5f);
        float sf = fmaf(0.5f, tanh_ap(zf), 0.5f);
        float tg = tanh_ap(zg);
        float so = fmaf(0.5f, tanh_ap(zo), 0.5f);
        float cn = fmaf(sf, c[p], si * tg);
        c[p] = cn;
        h[p] = so * tanh_ap(cn);
    }
}

__global__ void __launch_bounds__(TPB, 1)
multicell_lstm_kernel(
    const float* __restrict__ x,
    const float* __restrict__ Wlin, const float* __restrict__ blin,
    float* __restrict__ out)
{
    // all recurrent weights in smem: [0..99] whB, [100..199] whA
    __shared__ longlong2 s_w[200];
    const int tid = threadIdx.x;
    for (int i = tid; i < 200; i += TPB) s_w[i] = g_pack[i];
    __syncthreads();

    // element id; activity boundary is warp-uniform (148*224 vs 2*16384)
    const int e = (blockIdx.x * TPB + tid) >> 1;
    if (e >= BATCH) return;

    const int rbase = (tid & 1) * 5;

    // one-time divergent const reads -> registers (loop-invariant)
    ull bBif[5], bBgo[5], bAif[5], bAgo[5];
    ull wxBif[5], wxBgo[5], wxA0if[5], wxA0go[5], wxA1if[5], wxA1go[5];
    ull wA0if[5], wA0go[5];   // whA jj=0 own-row slice
#pragma unroll
    for (int p = 0; p < 5; p++){
        longlong2 vb   = c_w[OFF_BB   + rbase + p];
        longlong2 va   = c_w[OFF_BA   + rbase + p];
        longlong2 vxb  = c_w[OFF_WXB  + rbase + p];
        longlong2 vxa0 = c_w[OFF_WXA0 + rbase + p];
        longlong2 vxa1 = c_w[OFF_WXA1 + rbase + p];
        longlong2 vw0  = c_w[OFF_WHA  + rbase + p];   // jj=0 row of whA
        bBif[p]   = (ull)vb.x;   bBgo[p]   = (ull)vb.y;
        bAif[p]   = (ull)va.x;   bAgo[p]   = (ull)va.y;
        wxBif[p]  = (ull)vxb.x;  wxBgo[p]  = (ull)vxb.y;
        wxA0if[p] = (ull)vxa0.x; wxA0go[p] = (ull)vxa0.y;
        wxA1if[p] = (ull)vxa1.x; wxA1go[p] = (ull)vxa1.y;
        wA0if[p]  = (ull)vw0.x;  wA0go[p]  = (ull)vw0.y;
    }

    const float4* xp = reinterpret_cast<const float4*>(x) + (size_t)e * TPAIRS;

    float h[5], c[5];
#pragma unroll
    for (int p = 0; p < 5; p++){ h[p] = 0.0f; c[p] = 0.0f; }

    // software prefetch: xv holds step p's data, loaded one iteration ahead
    float4 xv = __ldg(&xp[0]);
    for (int p = 0; p < TPAIRS; p++){
        float4 xnext = __ldg(&xp[(p + 1) & (TPAIRS - 1)]);
        cell_step<1, false>(s_w,       wA0if, wA0go, wxBif,  wxBgo,  wxBif,  wxBgo,
                            bBif, bBgo, rbase, h, c, xv.x, 0.0f);
        cell_step<2, true >(s_w + 100, wA0if, wA0go, wxA0if, wxA0go, wxA1if, wxA1go,
                            bAif, bAgo, rbase, h, c, xv.z, xv.w);
        xv = xnext;
    }

    // out = sigmoid(h @ Wlin.T + blin): partial dot over owned dims + pair-sum
    float a = 0.0f;
#pragma unroll
    for (int p = 0; p < 5; p++) a = fmaf(h[p], __ldg(&Wlin[rbase + p]), a);
    a += __shfl_xor_sync(0xffffffffu, a, 1);
    if ((tid & 1) == 0)
        out[e] = fmaf(0.5f, tanh_ap(0.5f * (a + __ldg(&blin[0]))), 0.5f);
}

extern "C" void kernel_launch(void* const* d_in, const int* in_sizes, int n_in,
                              void* d_out, int out_size)
{
    const float* x    = (const float*)d_in[0];
    const float* WihA = (const float*)d_in[1];
    const float* WhhA = (const float*)d_in[2];
    const float* bihA = (const float*)d_in[3];
    const float* bhhA = (const float*)d_in[4];
    const float* WihB = (const float*)d_in[5];
    const float* WhhB = (const float*)d_in[6];
    const float* bihB = (const float*)d_in[7];
    const float* bhhB = (const float*)d_in[8];
    const float* Wlin = (const float*)d_in[9];
    const float* blin = (const float*)d_in[10];
    float* out = (float*)d_out;

    pack_kernel<<<1, 256>>>(WihA, WhhA, bihA, bhhA, WihB, WhhB, bihB, bhhB);

    void* g_pack_dev = nullptr;
    cudaGetSymbolAddress(&g_pack_dev, g_pack);
    cudaMemcpyToSymbolAsync(c_w, g_pack_dev, 250 * sizeof(longlong2), 0,
                            cudaMemcpyDeviceToDevice, 0);

    // 148 blocks x 224 threads: all SMs engaged, 112 elements/SM (was 128),
    // smem+regs loop with one weight row register-resident.
    dim3 grid(NBLK), block(TPB);
    multicell_lstm_kernel<<<grid, block>>>(x, Wlin, blin, out);
}

// round 13
// speedup vs baseline: 1.4667x; 1.0249x over previous
#include <cuda_runtime.h>

typedef unsigned long long ull;

#define HID 10
#define BATCH 16384
#define TPAIRS 1024
#define TPB 224
#define NBLK 148

// ---------- g_pack / c_w layout (250 longlong2), identical to r10-r12 ----------
#define OFF_WHB   0
#define OFF_WHA   100
#define OFF_WXB   200
#define OFF_WXA0  210
#define OFF_WXA1  220
#define OFF_BB    230
#define OFF_BA    240

__constant__ longlong2 c_w[250];
__device__   longlong2 g_pack[250];

// ---------- packed fp32x2 helpers ----------
__device__ __forceinline__ ull pack2(float lo, float hi){
    ull r; asm("mov.b64 %0, {%1, %2};" : "=l"(r) : "f"(lo), "f"(hi)); return r;
}
__device__ __forceinline__ ull bcast2(float v){
    ull r; asm("mov.b64 %0, {%1, %1};" : "=l"(r) : "f"(v)); return r;
}
__device__ __forceinline__ void unpack2(ull v, float &lo, float &hi){
    asm("mov.b64 {%0, %1}, %2;" : "=f"(lo), "=f"(hi) : "l"(v));
}
__device__ __forceinline__ ull ffma2(ull a, ull b, ull c){
    ull d; asm("fma.rn.f32x2 %0, %1, %2, %3;" : "=l"(d) : "l"(a), "l"(b), "l"(c)); return d;
}
__device__ __forceinline__ float tanh_ap(float x){
    float r; asm("tanh.approx.f32 %0, %1;" : "=f"(r) : "f"(x)); return r;
}

// ---------- pack kernel (identical to r10-r12, known-good) ----------
__global__ void pack_kernel(
    const float* __restrict__ WihA, const float* __restrict__ WhhA,
    const float* __restrict__ bihA, const float* __restrict__ bhhA,
    const float* __restrict__ WihB, const float* __restrict__ WhhB,
    const float* __restrict__ bihB, const float* __restrict__ bhhB)
{
    int idx = threadIdx.x;
    if (idx < 200){
        int cell = idx / 100;          // 0 = B, 1 = A
        int rem  = idx % 100;          // jj*10 + r*5 + p
        int jj = rem / 10;
        int r  = (rem % 10) / 5;
        int p  = rem % 5;
        int aj = (jj < 5) ? (5*r + jj) : (5*(1-r) + (jj-5));
        int d  = 5*r + p;
        const float* W = cell ? WhhA : WhhB;
        g_pack[(cell ? OFF_WHA : OFF_WHB) + rem] = make_longlong2(
            (long long)pack2(0.5f*W[(      d)*HID + aj], 0.5f*W[(  HID+d)*HID + aj]),
            (long long)pack2(     W[(2*HID+d)*HID + aj], 0.5f*W[(3*HID+d)*HID + aj]));
    } else if (idx < 250){
        int k = idx - 200;
        int grp = k / 10;              // 0 wxB, 1 wxA0, 2 wxA1, 3 bB, 4 bA
        int rp  = k % 10;              // r*5 + p
        int r = rp / 5, p = rp % 5;
        int d = 5*r + p;
        longlong2 v;
        if (grp == 0){
            v = make_longlong2(
                (long long)pack2(0.5f*WihB[d],         0.5f*WihB[HID+d]),
                (long long)pack2(     WihB[2*HID+d],   0.5f*WihB[3*HID+d]));
        } else if (grp == 1){
            v = make_longlong2(
                (long long)pack2(0.5f*WihA[(      d)*2], 0.5f*WihA[(  HID+d)*2]),
                (long long)pack2(     WihA[(2*HID+d)*2], 0.5f*WihA[(3*HID+d)*2]));
        } else if (grp == 2){
            v = make_longlong2(
                (long long)pack2(0.5f*WihA[(      d)*2+1], 0.5f*WihA[(  HID+d)*2+1]),
                (long long)pack2(     WihA[(2*HID+d)*2+1], 0.5f*WihA[(3*HID+d)*2+1]));
        } else if (grp == 3){
            v = make_longlong2(
                (long long)pack2(0.5f*(bihB[d]       + bhhB[d]),
                                 0.5f*(bihB[HID+d]   + bhhB[HID+d])),
                (long long)pack2(     (bihB[2*HID+d] + bhhB[2*HID+d]),
                                 0.5f*(bihB[3*HID+d] + bhhB[3*HID+d])));
        } else {
            v = make_longlong2(
                (long long)pack2(0.5f*(bihA[d]       + bhhA[d]),
                                 0.5f*(bihA[HID+d]   + bhhA[HID+d])),
                (long long)pack2(     (bihA[2*HID+d] + bhhA[2*HID+d]),
                                 0.5f*(bihA[3*HID+d] + bhhA[3*HID+d])));
        }
        g_pack[idx] = v;
    }
}

// ---------- pure smem+reg LSTM cell step; register-resident jj=0 row ----------
template<int NIN>
__device__ __forceinline__ void cell_step(
    const longlong2* __restrict__ s_wh,
    const ull* w0if, const ull* w0go,     // own jj=0 row (registers)
    const ull* wx0if, const ull* wx0go,
    const ull* wx1if, const ull* wx1go,
    const ull* bif, const ull* bgo,
    int rbase, float h[5], float c[5], float x0, float x1)
{
    // partner-h exchange first: shfl latency hides under own-row matvec
    float hp[5];
#pragma unroll
    for (int p = 0; p < 5; p++) hp[p] = __shfl_xor_sync(0xffffffffu, h[p], 1);

    ull aIF[5], aGO[5];
#pragma unroll
    for (int p = 0; p < 5; p++){ aIF[p] = bif[p]; aGO[p] = bgo[p]; }

    // own jj=0 row from registers (no load)
    {
        ull hb = bcast2(h[0]);
#pragma unroll
        for (int p = 0; p < 5; p++){
            aIF[p] = ffma2(w0if[p], hb, aIF[p]);
            aGO[p] = ffma2(w0go[p], hb, aGO[p]);
        }
    }
    // smem own rows jj = 1..4
#pragma unroll
    for (int jj = 1; jj < 5; jj++){
        ull hb = bcast2(h[jj]);
#pragma unroll
        for (int p = 0; p < 5; p++){
            longlong2 w = s_wh[jj*10 + rbase + p];
            aIF[p] = ffma2((ull)w.x, hb, aIF[p]);
            aGO[p] = ffma2((ull)w.y, hb, aGO[p]);
        }
    }
    // smem partner rows jj = 5..9 (hp ready by now)
#pragma unroll
    for (int jj = 5; jj < 10; jj++){
        ull hb = bcast2(hp[jj-5]);
#pragma unroll
        for (int p = 0; p < 5; p++){
            longlong2 w = s_wh[jj*10 + rbase + p];
            aIF[p] = ffma2((ull)w.x, hb, aIF[p]);
            aGO[p] = ffma2((ull)w.y, hb, aGO[p]);
        }
    }
    // x contributions LAST: matvec above covers the x LDG latency
    {
        ull xb = bcast2(x0);
#pragma unroll
        for (int p = 0; p < 5; p++){
            aIF[p] = ffma2(wx0if[p], xb, aIF[p]);
            aGO[p] = ffma2(wx0go[p], xb, aGO[p]);
        }
    }
    if (NIN == 2){
        ull xb = bcast2(x1);
#pragma unroll
        for (int p = 0; p < 5; p++){
            aIF[p] = ffma2(wx1if[p], xb, aIF[p]);
            aGO[p] = ffma2(wx1go[p], xb, aGO[p]);
        }
    }
    // epilogue: 5 MUFU per owned dim
#pragma unroll
    for (int p = 0; p < 5; p++){
        float zi, zf, zg, zo;
        unpack2(aIF[p], zi, zf);
        unpack2(aGO[p], zg, zo);
        float si = fmaf(0.5f, tanh_ap(zi), 0.5f);
        float sf = fmaf(0.5f, tanh_ap(zf), 0.5f);
        float tg = tanh_ap(zg);
        float so = fmaf(0.5f, tanh_ap(zo), 0.5f);
        float cn = fmaf(sf, c[p], si * tg);
        c[p] = cn;
        h[p] = so * tanh_ap(cn);
    }
}

__global__ void __launch_bounds__(TPB, 1)
multicell_lstm_kernel(
    const float* __restrict__ x,
    const float* __restrict__ Wlin, const float* __restrict__ blin,
    float* __restrict__ out)
{
    // all recurrent weights in smem: [0..99] whB, [100..199] whA
    __shared__ longlong2 s_w[200];
    const int tid = threadIdx.x;
    for (int i = tid; i < 200; i += TPB) s_w[i] = g_pack[i];
    __syncthreads();

    // element id; activity boundary is warp-uniform (148*224 vs 2*16384)
    const int e = (blockIdx.x * TPB + tid) >> 1;
    if (e >= BATCH) return;

    const int rbase = (tid & 1) * 5;

    // one-time divergent const reads -> registers (loop-invariant)
    ull bBif[5], bBgo[5], bAif[5], bAgo[5];
    ull wxBif[5], wxBgo[5], wxA0if[5], wxA0go[5], wxA1if[5], wxA1go[5];
    ull wA0if[5], wA0go[5];   // whA jj=0 own-row slice
    ull wB0if[5], wB0go[5];   // whB jj=0 own-row slice
#pragma unroll
    for (int p = 0; p < 5; p++){
        longlong2 vb   = c_w[OFF_BB   + rbase + p];
        longlong2 va   = c_w[OFF_BA   + rbase + p];
        longlong2 vxb  = c_w[OFF_WXB  + rbase + p];
        longlong2 vxa0 = c_w[OFF_WXA0 + rbase + p];
        longlong2 vxa1 = c_w[OFF_WXA1 + rbase + p];
        longlong2 vwa0 = c_w[OFF_WHA  + rbase + p];   // jj=0 row of whA
        longlong2 vwb0 = c_w[OFF_WHB  + rbase + p];   // jj=0 row of whB
        bBif[p]   = (ull)vb.x;   bBgo[p]   = (ull)vb.y;
        bAif[p]   = (ull)va.x;   bAgo[p]   = (ull)va.y;
        wxBif[p]  = (ull)vxb.x;  wxBgo[p]  = (ull)vxb.y;
        wxA0if[p] = (ull)vxa0.x; wxA0go[p] = (ull)vxa0.y;
        wxA1if[p] = (ull)vxa1.x; wxA1go[p] = (ull)vxa1.y;
        wA0if[p]  = (ull)vwa0.x; wA0go[p]  = (ull)vwa0.y;
        wB0if[p]  = (ull)vwb0.x; wB0go[p]  = (ull)vwb0.y;
    }

    const float4* xp = reinterpret_cast<const float4*>(x) + (size_t)e * TPAIRS;

    float h[5], c[5];
#pragma unroll
    for (int p = 0; p < 5; p++){ h[p] = 0.0f; c[p] = 0.0f; }

    // software prefetch: xv holds step p's data, loaded one iteration ahead
    float4 xv = __ldg(&xp[0]);
    for (int p = 0; p < TPAIRS; p++){
        float4 xnext = __ldg(&xp[(p + 1) & (TPAIRS - 1)]);
        cell_step<1>(s_w,       wB0if, wB0go, wxBif,  wxBgo,  wxBif,  wxBgo,
                     bBif, bBgo, rbase, h, c, xv.x, 0.0f);
        cell_step<2>(s_w + 100, wA0if, wA0go, wxA0if, wxA0go, wxA1if, wxA1go,
                     bAif, bAgo, rbase, h, c, xv.z, xv.w);
        xv = xnext;
    }

    // out = sigmoid(h @ Wlin.T + blin): partial dot over owned dims + pair-sum
    float a = 0.0f;
#pragma unroll
    for (int p = 0; p < 5; p++) a = fmaf(h[p], __ldg(&Wlin[rbase + p]), a);
    a += __shfl_xor_sync(0xffffffffu, a, 1);
    if ((tid & 1) == 0)
        out[e] = fmaf(0.5f, tanh_ap(0.5f * (a + __ldg(&blin[0]))), 0.5f);
}

extern "C" void kernel_launch(void* const* d_in, const int* in_sizes, int n_in,
                              void* d_out, int out_size)
{
    const float* x    = (const float*)d_in[0];
    const float* WihA = (const float*)d_in[1];
    const float* WhhA = (const float*)d_in[2];
    const float* bihA = (const float*)d_in[3];
    const float* bhhA = (const float*)d_in[4];
    const float* WihB = (const float*)d_in[5];
    const float* WhhB = (const float*)d_in[6];
    const float* bihB = (const float*)d_in[7];
    const float* bhhB = (const float*)d_in[8];
    const float* Wlin = (const float*)d_in[9];
    const float* blin = (const float*)d_in[10];
    float* out = (float*)d_out;

    pack_kernel<<<1, 256>>>(WihA, WhhA, bihA, bhhA, WihB, WhhB, bihB, bhhB);

    void* g_pack_dev = nullptr;
    cudaGetSymbolAddress(&g_pack_dev, g_pack);
    cudaMemcpyToSymbolAsync(c_w, g_pack_dev, 250 * sizeof(longlong2), 0,
                            cudaMemcpyDeviceToDevice, 0);

    // 148 blocks x 224 threads; both cells' jj=0 rows register-resident
    // -> 90 LDS.128/warp/pair-step (wavefront wall 1410 -> 1270 per SM)
    dim3 grid(NBLK), block(TPB);
    multicell_lstm_kernel<<<grid, block>>>(x, Wlin, blin, out);
}